// round 7
// baseline (speedup 1.0000x reference)
#include <cuda_runtime.h>
#include <math.h>
#include <stdint.h>

// Problem constants
#define BATCH 4
#define SEQ   2048
#define CMODEL 1024
#define NHEAD 16
#define HDIM  64
#define BH    (BATCH*NHEAD)          // 64
#define MROWS (BATCH*SEQ)            // 8192

// Scratch (allocation-free rule: __device__ globals)
__device__ float g_Q[(size_t)BH*SEQ*HDIM];   // tf32, pre-scaled by 0.125*log2e
__device__ float g_K[(size_t)BH*SEQ*HDIM];   // tf32
__device__ float g_V[(size_t)BH*SEQ*HDIM];   // tf32
__device__ float g_A[(size_t)MROWS*CMODEL];  // attention out, tf32-rounded
__device__ float g_Xr[(size_t)MROWS*CMODEL];     // x, tf32-rounded
__device__ float g_Wqkv[(size_t)3*CMODEL*CMODEL];// qkv_w, tf32-rounded
__device__ float g_Wo[(size_t)CMODEL*CMODEL];    // out_w, tf32-rounded

// log2(10000)/64
#define ROPE_L2 0.20762050593060493f
// 0.125 * log2(e)
#define QSCALE 0.18033688011112042f

#define KPAD 20   // GEMM k-stride in shared

__device__ __forceinline__ uint32_t f2tf32(float f) {
    uint32_t r;
    asm("cvt.rna.tf32.f32 %0, %1;" : "=r"(r) : "f"(f));
    return r;
}
__device__ __forceinline__ float tf32f(float f) { return __uint_as_float(f2tf32(f)); }
__device__ __forceinline__ float ex2(float x) {
    float r;
    asm("ex2.approx.f32 %0, %1;" : "=f"(r) : "f"(x));
    return r;
}

__device__ __forceinline__ void cp16(float* s, const float* g) {
    uint32_t sa = (uint32_t)__cvta_generic_to_shared(s);
    asm volatile("cp.async.cg.shared.global [%0], [%1], 16;\n" :: "r"(sa), "l"(g));
}
#define CP_COMMIT asm volatile("cp.async.commit_group;\n" ::: "memory")
#define CP_WAIT0  asm volatile("cp.async.wait_group 0;\n" ::: "memory")
#define CP_WAIT1  asm volatile("cp.async.wait_group 1;\n" ::: "memory")

__device__ __forceinline__ void mma_tf32(float4& d, const uint32_t* a, const uint32_t* b) {
    asm volatile(
        "mma.sync.aligned.m16n8k8.row.col.f32.tf32.tf32.f32 "
        "{%0,%1,%2,%3}, {%4,%5,%6,%7}, {%8,%9}, {%0,%1,%2,%3};\n"
        : "+f"(d.x), "+f"(d.y), "+f"(d.z), "+f"(d.w)
        : "r"(a[0]), "r"(a[1]), "r"(a[2]), "r"(a[3]), "r"(b[0]), "r"(b[1]));
}

// ---------------------------------------------------------------------------
// Kernel 0: tf32 pre-round (float4 vectorized)
// ---------------------------------------------------------------------------
__global__ __launch_bounds__(256) void round_kernel(
    const float4* __restrict__ in, float4* __restrict__ outp, int n4)
{
    const int i = blockIdx.x * 256 + threadIdx.x;
    if (i < n4) {
        float4 v = in[i];
        float4 o;
        o.x = tf32f(v.x); o.y = tf32f(v.y); o.z = tf32f(v.z); o.w = tf32f(v.w);
        outp[i] = o;
    }
}

// ---------------------------------------------------------------------------
// GEMM mainloop: C[128x128] tile of A[M][1024] * B[N][1024]^T.
// 3-stage cp.async ring, ONE __syncthreads per k-tile, raw-bit tf32 frags
// (inputs pre-rounded). Dynamic smem: sA 3*128*KPAD, sB 3*128*KPAD.
// ---------------------------------------------------------------------------
#define GSTAGE(B, KT) do {                                                          \
    const float* pa_ = ga + (KT) * 16;                                              \
    const float* pb_ = gb + (KT) * 16;                                              \
    float* da_ = sAw + (B) * 128 * KPAD;                                            \
    float* db_ = sBw + (B) * 128 * KPAD;                                            \
    cp16(da_, pa_); cp16(da_ + 4, pa_ + 4);                                         \
    cp16(db_, pb_); cp16(db_ + 4, pb_ + 4);                                         \
    CP_COMMIT;                                                                      \
} while (0)

#define GEMM_MAINLOOP(APTR, BPTR)                                                   \
    extern __shared__ float smbuf[];                                                \
    float* sA = smbuf;                                                              \
    float* sB = smbuf + 3 * 128 * KPAD;                                             \
    const int tid = threadIdx.x;                                                    \
    const int w = tid >> 5, lane = tid & 31, g = lane >> 2, tg = lane & 3;          \
    const int wm = (w & 1) * 64, wn = (w >> 1) * 32;                                \
    const int m0 = blockIdx.y * 128, n0 = blockIdx.x * 128;                         \
    const int lr = tid >> 1, lc = (tid & 1) * 8;                                    \
    const float* ga = (APTR) + (size_t)(m0 + lr) * CMODEL + lc;                     \
    const float* gb = (BPTR) + (size_t)(n0 + lr) * CMODEL + lc;                     \
    float* sAw = sA + lr * KPAD + lc;                                               \
    float* sBw = sB + lr * KPAD + lc;                                               \
    float4 acc[4][4];                                                               \
    _Pragma("unroll")                                                               \
    for (int i = 0; i < 4; i++)                                                     \
        _Pragma("unroll")                                                           \
        for (int j = 0; j < 4; j++) acc[i][j] = make_float4(0.f, 0.f, 0.f, 0.f);    \
    GSTAGE(0, 0); GSTAGE(1, 1);                                                     \
    for (int kt = 0; kt < 64; kt++) {                                               \
        if (kt < 63) { CP_WAIT1; } else { CP_WAIT0; }                               \
        __syncthreads();                                                            \
        if (kt + 2 < 64) GSTAGE((kt + 2) % 3, kt + 2);                              \
        const float* sAb = sA + (kt % 3) * 128 * KPAD;                              \
        const float* sBb = sB + (kt % 3) * 128 * KPAD;                              \
        _Pragma("unroll")                                                           \
        for (int ks = 0; ks < 2; ks++) {                                            \
            const int kk = ks * 8;                                                  \
            uint32_t af[4][4], bf[4][2];                                            \
            _Pragma("unroll")                                                       \
            for (int mi = 0; mi < 4; mi++) {                                        \
                const int rbase = wm + mi * 16;                                     \
                af[mi][0] = __float_as_uint(sAb[(rbase + g) * KPAD + kk + tg]);     \
                af[mi][1] = __float_as_uint(sAb[(rbase + g + 8) * KPAD + kk + tg]); \
                af[mi][2] = __float_as_uint(sAb[(rbase + g) * KPAD + kk + tg + 4]); \
                af[mi][3] = __float_as_uint(sAb[(rbase + g + 8) * KPAD + kk + tg + 4]); \
            }                                                                       \
            _Pragma("unroll")                                                       \
            for (int ni = 0; ni < 4; ni++) {                                        \
                const int cbase = wn + ni * 8;                                      \
                bf[ni][0] = __float_as_uint(sBb[(cbase + g) * KPAD + kk + tg]);     \
                bf[ni][1] = __float_as_uint(sBb[(cbase + g) * KPAD + kk + tg + 4]); \
            }                                                                       \
            _Pragma("unroll")                                                       \
            for (int mi = 0; mi < 4; mi++)                                          \
                _Pragma("unroll")                                                   \
                for (int ni = 0; ni < 4; ni++)                                      \
                    mma_tf32(acc[mi][ni], af[mi], bf[ni]);                          \
        }                                                                           \
    }

#define GEMM_SMEM (2 * 3 * 128 * KPAD * 4)   // 61440 bytes

// ---------------------------------------------------------------------------
// Kernel 1: QKV GEMM + bias + RoPE -> g_Q (scaled, tf32), g_K (tf32), g_V (tf32)
// ---------------------------------------------------------------------------
__global__ __launch_bounds__(256) void qkv_gemm_kernel(
    const float* __restrict__ bias)
{
    GEMM_MAINLOOP(g_Xr, g_Wqkv)

    #pragma unroll
    for (int mi = 0; mi < 4; mi++) {
        #pragma unroll
        for (int ni = 0; ni < 4; ni++) {
            float4 c = acc[mi][ni];
            const int col = n0 + wn + ni * 8 + 2 * tg;   // even
            const int which = col >> 10;                 // 0=q,1=k,2=v
            const int cc = col & 1023;
            const int h = cc >> 6;
            const int d0 = cc & 63;
            const float b0 = bias[col], b1 = bias[col + 1];
            const float invf = exp2f(-(float)d0 * ROPE_L2);
            const int r0 = m0 + wm + mi * 16 + g;
            #pragma unroll
            for (int half = 0; half < 2; half++) {
                const int r = r0 + half * 8;
                float v0 = (half ? c.z : c.x) + b0;
                float v1 = (half ? c.w : c.y) + b1;
                const int b = r >> 11;
                const int t = r & (SEQ - 1);
                const size_t base = ((size_t)(b * NHEAD + h) * SEQ + t) * HDIM + d0;
                if (which == 2) {
                    g_V[base]     = tf32f(v0);
                    g_V[base + 1] = tf32f(v1);
                } else {
                    float s, co;
                    sincosf((float)t * invf, &s, &co);
                    float r0v = v0 * co - v1 * s;
                    float r1v = v0 * s  + v1 * co;
                    if (which == 0) {  // pre-scale Q by 1/sqrt(64) * log2(e)
                        g_Q[base]     = tf32f(r0v * QSCALE);
                        g_Q[base + 1] = tf32f(r1v * QSCALE);
                    } else {
                        g_K[base]     = tf32f(r0v);
                        g_K[base + 1] = tf32f(r1v);
                    }
                }
            }
        }
    }
}

// ---------------------------------------------------------------------------
// Kernel 2: causal flash attention, tf32 mma; base-2 softmax.
// 128 threads (4 warps); Br=64 (16 rows/warp), Bc=32; 3-stage cp.async ring,
// ONE __syncthreads per tile; P in registers (shuffle permute).
// Dynamic smem: Ks 3*32*68, Vs 3*32*72  (53760 bytes)
// ---------------------------------------------------------------------------
#define KS(B,R,C) sK[((B)*32+(R))*68+(C)]
#define VS(B,R,C) sV[((B)*32+(R))*72+(C)]
#define ATTN_SMEM ((3*32*68 + 3*32*72) * 4)

__global__ __launch_bounds__(128, 4) void attn_kernel()
{
    extern __shared__ float smb[];
    float* sK = smb;
    float* sV = smb + 3 * 32 * 68;

    const int tid = threadIdx.x;
    const int w = tid >> 5, lane = tid & 31, g = lane >> 2, tg = lane & 3;
    const int wq0 = w * 16;
    const int bh = blockIdx.y;
    const int q0 = ((int)gridDim.x - 1 - (int)blockIdx.x) * 64;  // heavy blocks first
    const size_t bhbase = (size_t)bh * SEQ * HDIM;
    const int lr0 = wq0 + g, lr1 = wq0 + g + 8;

#define ATTN_STAGE(B, S0) do {                                                   \
        _Pragma("unroll")                                                        \
        for (int i = 0; i < 4; i++) {                                            \
            const int idx = tid + i * 128;                                       \
            const int r = idx >> 4, c = (idx & 15) * 4;                          \
            cp16(&KS(B, r, c), g_K + bhbase + (size_t)((S0) + r) * HDIM + c);    \
            cp16(&VS(B, r, c), g_V + bhbase + (size_t)((S0) + r) * HDIM + c);    \
        }                                                                        \
        CP_COMMIT;                                                               \
    } while (0)

    const int ntiles = q0 / 32 + 2;
    ATTN_STAGE(0, 0);
    ATTN_STAGE(1, 32);

    // Q fragments straight from gmem (already tf32, already scaled)
    uint32_t qf[8][4];
    {
        const float* qb = g_Q + bhbase + (size_t)q0 * HDIM;
        #pragma unroll
        for (int ks = 0; ks < 8; ks++) {
            const int kk = ks * 8;
            qf[ks][0] = __float_as_uint(qb[(size_t)lr0 * HDIM + kk + tg]);
            qf[ks][1] = __float_as_uint(qb[(size_t)lr1 * HDIM + kk + tg]);
            qf[ks][2] = __float_as_uint(qb[(size_t)lr0 * HDIM + kk + tg + 4]);
            qf[ks][3] = __float_as_uint(qb[(size_t)lr1 * HDIM + kk + tg + 4]);
        }
    }

    float4 o[8];
    #pragma unroll
    for (int ni = 0; ni < 8; ni++) o[ni] = make_float4(0.f, 0.f, 0.f, 0.f);
    float m0r = -1e30f, m1r = -1e30f, l0 = 0.f, l1 = 0.f;

    for (int it = 0; it < ntiles; it++) {
        const int s0 = it * 32;
        if (it < ntiles - 1) { CP_WAIT1; } else { CP_WAIT0; }
        __syncthreads();
        if (it + 2 < ntiles) ATTN_STAGE((it + 2) % 3, s0 + 64);
        const int b = it % 3;

        // ---- S = Q * K^T (64 warp rows x 32 keys), log2-scaled ----
        float4 s[4];
        #pragma unroll
        for (int ni = 0; ni < 4; ni++) s[ni] = make_float4(0.f, 0.f, 0.f, 0.f);
        #pragma unroll
        for (int ks = 0; ks < 8; ks++) {
            const int kk = ks * 8;
            #pragma unroll
            for (int ni = 0; ni < 4; ni++) {
                uint32_t bfr[2];
                bfr[0] = __float_as_uint(KS(b, ni * 8 + g, kk + tg));
                bfr[1] = __float_as_uint(KS(b, ni * 8 + g, kk + tg + 4));
                mma_tf32(s[ni], qf[ks], bfr);
            }
        }

        // ---- causal mask (only tiles that can cross the diagonal) ----
        if (s0 + 31 > q0) {
            #pragma unroll
            for (int ni = 0; ni < 4; ni++) {
                const int c0 = s0 + ni * 8 + 2 * tg, c1 = c0 + 1;
                const int t0 = q0 + lr0, t1 = q0 + lr1;
                if (c0 > t0) s[ni].x = -1e30f;
                if (c1 > t0) s[ni].y = -1e30f;
                if (c0 > t1) s[ni].z = -1e30f;
                if (c1 > t1) s[ni].w = -1e30f;
            }
        }

        // ---- online softmax (base 2) ----
        float tm0 = -1e30f, tm1 = -1e30f;
        #pragma unroll
        for (int ni = 0; ni < 4; ni++) {
            tm0 = fmaxf(tm0, fmaxf(s[ni].x, s[ni].y));
            tm1 = fmaxf(tm1, fmaxf(s[ni].z, s[ni].w));
        }
        tm0 = fmaxf(tm0, __shfl_xor_sync(0xffffffffu, tm0, 1));
        tm0 = fmaxf(tm0, __shfl_xor_sync(0xffffffffu, tm0, 2));
        tm1 = fmaxf(tm1, __shfl_xor_sync(0xffffffffu, tm1, 1));
        tm1 = fmaxf(tm1, __shfl_xor_sync(0xffffffffu, tm1, 2));

        const float mn0 = fmaxf(m0r, tm0), mn1 = fmaxf(m1r, tm1);
        const float cr0 = ex2(m0r - mn0), cr1 = ex2(m1r - mn1);
        m0r = mn0; m1r = mn1;

        float ls0 = 0.f, ls1 = 0.f;
        #pragma unroll
        for (int ni = 0; ni < 4; ni++) {
            s[ni].x = ex2(s[ni].x - mn0);
            s[ni].y = ex2(s[ni].y - mn0);
            s[ni].z = ex2(s[ni].z - mn1);
            s[ni].w = ex2(s[ni].w - mn1);
            ls0 += s[ni].x + s[ni].y;
            ls1 += s[ni].z + s[ni].w;
        }
        ls0 += __shfl_xor_sync(0xffffffffu, ls0, 1);
        ls0 += __shfl_xor_sync(0xffffffffu, ls0, 2);
        ls1 += __shfl_xor_sync(0xffffffffu, ls1, 1);
        ls1 += __shfl_xor_sync(0xffffffffu, ls1, 2);
        l0 = l0 * cr0 + ls0;
        l1 = l1 * cr1 + ls1;

        #pragma unroll
        for (int ni = 0; ni < 8; ni++) {
            o[ni].x *= cr0; o[ni].y *= cr0;
            o[ni].z *= cr1; o[ni].w *= cr1;
        }

        // ---- P (registers) -> A-fragment layout via shuffles; O += P * V ----
        uint32_t px[4], py[4], pz[4], pw[4];
        #pragma unroll
        for (int ni = 0; ni < 4; ni++) {
            px[ni] = f2tf32(s[ni].x); py[ni] = f2tf32(s[ni].y);
            pz[ni] = f2tf32(s[ni].z); pw[ni] = f2tf32(s[ni].w);
        }
        const int src0 = (lane & ~3) | (tg >> 1);
        const int src1 = src0 + 2;
        #pragma unroll
        for (int ks2 = 0; ks2 < 4; ks2++) {
            const uint32_t x0 = __shfl_sync(0xffffffffu, px[ks2], src0);
            const uint32_t y0 = __shfl_sync(0xffffffffu, py[ks2], src0);
            const uint32_t z0 = __shfl_sync(0xffffffffu, pz[ks2], src0);
            const uint32_t w0 = __shfl_sync(0xffffffffu, pw[ks2], src0);
            const uint32_t x1 = __shfl_sync(0xffffffffu, px[ks2], src1);
            const uint32_t y1 = __shfl_sync(0xffffffffu, py[ks2], src1);
            const uint32_t z1 = __shfl_sync(0xffffffffu, pz[ks2], src1);
            const uint32_t w1 = __shfl_sync(0xffffffffu, pw[ks2], src1);
            uint32_t af[4];
            af[0] = (tg & 1) ? y0 : x0;
            af[1] = (tg & 1) ? w0 : z0;
            af[2] = (tg & 1) ? y1 : x1;
            af[3] = (tg & 1) ? w1 : z1;
            const int kk = ks2 * 8;
            #pragma unroll
            for (int ni = 0; ni < 8; ni++) {
                uint32_t bfr[2];
                bfr[0] = __float_as_uint(VS(b, kk + tg, ni * 8 + g));
                bfr[1] = __float_as_uint(VS(b, kk + tg + 4, ni * 8 + g));
                mma_tf32(o[ni], af, bfr);
            }
        }
    }

    // ---- epilogue: normalize, tf32-round, write to g_A ----
    const float inv0 = 1.f / l0, inv1 = 1.f / l1;
    const int b2 = bh >> 4, h = bh & 15;
    const int t0 = q0 + lr0, t1 = q0 + lr1;
    float* d0p = g_A + ((size_t)(b2 * SEQ + t0)) * CMODEL + h * HDIM;
    float* d1p = g_A + ((size_t)(b2 * SEQ + t1)) * CMODEL + h * HDIM;
    #pragma unroll
    for (int ni = 0; ni < 8; ni++) {
        const int c0 = ni * 8 + 2 * tg;
        d0p[c0]     = tf32f(o[ni].x * inv0);
        d0p[c0 + 1] = tf32f(o[ni].y * inv0);
        d1p[c0]     = tf32f(o[ni].z * inv1);
        d1p[c0 + 1] = tf32f(o[ni].w * inv1);
    }
#undef ATTN_STAGE
}

// ---------------------------------------------------------------------------
// Kernel 3: output projection + bias -> d_out
// ---------------------------------------------------------------------------
__global__ __launch_bounds__(256) void proj_gemm_kernel(
    const float* __restrict__ bias, float* __restrict__ out)
{
    GEMM_MAINLOOP(g_A, g_Wo)

    #pragma unroll
    for (int mi = 0; mi < 4; mi++) {
        #pragma unroll
        for (int ni = 0; ni < 4; ni++) {
            float4 c = acc[mi][ni];
            const int col = n0 + wn + ni * 8 + 2 * tg;
            const float b0 = bias[col], b1 = bias[col + 1];
            const int r0 = m0 + wm + mi * 16 + g;
            out[(size_t)r0 * CMODEL + col]           = c.x + b0;
            out[(size_t)r0 * CMODEL + col + 1]       = c.y + b1;
            out[(size_t)(r0 + 8) * CMODEL + col]     = c.z + b0;
            out[(size_t)(r0 + 8) * CMODEL + col + 1] = c.w + b1;
        }
    }
}

// ---------------------------------------------------------------------------
extern "C" void kernel_launch(void* const* d_in, const int* in_sizes, int n_in,
                              void* d_out, int out_size)
{
    const float* x      = (const float*)d_in[0];
    const float* qkv_w  = (const float*)d_in[1];
    const float* qkv_b  = (const float*)d_in[2];
    const float* out_w  = (const float*)d_in[3];
    const float* out_b  = (const float*)d_in[4];
    float* out = (float*)d_out;

    cudaFuncSetAttribute(qkv_gemm_kernel, cudaFuncAttributeMaxDynamicSharedMemorySize, GEMM_SMEM);
    cudaFuncSetAttribute(proj_gemm_kernel, cudaFuncAttributeMaxDynamicSharedMemorySize, GEMM_SMEM);
    cudaFuncSetAttribute(attn_kernel, cudaFuncAttributeMaxDynamicSharedMemorySize, ATTN_SMEM);

    // tf32 pre-round of GEMM operands
    float* xr; cudaGetSymbolAddress((void**)&xr, g_Xr);
    float* wq; cudaGetSymbolAddress((void**)&wq, g_Wqkv);
    float* wo; cudaGetSymbolAddress((void**)&wo, g_Wo);
    {
        const int n4x = MROWS * CMODEL / 4;          // 2097152
        const int n4q = 3 * CMODEL * CMODEL / 4;     // 786432
        const int n4o = CMODEL * CMODEL / 4;         // 262144
        round_kernel<<<(n4x + 255) / 256, 256>>>((const float4*)x, (float4*)xr, n4x);
        round_kernel<<<(n4q + 255) / 256, 256>>>((const float4*)qkv_w, (float4*)wq, n4q);
        round_kernel<<<(n4o + 255) / 256, 256>>>((const float4*)out_w, (float4*)wo, n4o);
    }

    qkv_gemm_kernel<<<dim3(3*CMODEL/128, MROWS/128), 256, GEMM_SMEM>>>(qkv_b);
    attn_kernel<<<dim3(SEQ/64, BH), 128, ATTN_SMEM>>>();
    proj_gemm_kernel<<<dim3(CMODEL/128, MROWS/128), 256, GEMM_SMEM>>>(out_b, out);
}